// round 11
// baseline (speedup 1.0000x reference)
#include <cuda_runtime.h>
#include <cstdint>

// ---- problem dims ----
#define T_TOK 2048
#define HID   2048
#define EXP   8
#define N1    4096
#define K2    16384
#define K2P   16416   // K2 + 32: bias folded into K (cols 16384..16391 = rw / down_b)

// ---- tiling ----
constexpr int BM = 128, BN = 256, BK = 32;
constexpr int NTHR = 256;             // 8 warps: 2 (m) x 4 (n), warp tile 64x64
constexpr int NSTG = 4;
constexpr int ASTR = 36, BSTR = 36;   // words/row (32 data + 4 pad): conflict-free
constexpr int ABYTES = BM * ASTR * 4;       // 18432
constexpr int BBYTES = BN * BSTR * 4;       // 36864
constexpr int STG = ABYTES + BBYTES;        // 55296
constexpr int SMEM_SZ = NSTG * STG;         // 221184

// ---- scratch (device globals; allocation forbidden) ----
__device__ __align__(1024) float g_xc [(size_t)T_TOK * HID];      // tf32-rounded x
__device__ __align__(1024) float g_w1t[(size_t)EXP * N1 * HID];   // [e][n][h]
__device__ __align__(1024) float g_w2t[(size_t)HID * K2P];        // [h][k] (+bias tail)
__device__ __align__(1024) float g_fw [(size_t)T_TOK * K2P];      // rw-scaled GLU (+rw tail)

// ===================== helpers =====================
__device__ __forceinline__ uint32_t smem_u32(const void* p) {
    uint32_t a;
    asm("{ .reg .u64 t; cvta.to.shared.u64 t, %1; cvt.u32.u64 %0, t; }" : "=r"(a) : "l"(p));
    return a;
}
__device__ __forceinline__ uint32_t f2tf(float f) {
    uint32_t u; asm("cvt.rna.tf32.f32 %0, %1;" : "=r"(u) : "f"(f)); return u;
}
__device__ __forceinline__ void mma8(float* c, const uint32_t* a, const uint32_t* b) {
    asm volatile(
        "mma.sync.aligned.m16n8k8.row.col.f32.tf32.tf32.f32 "
        "{%0,%1,%2,%3}, {%4,%5,%6,%7}, {%8,%9}, {%0,%1,%2,%3};"
        : "+f"(c[0]), "+f"(c[1]), "+f"(c[2]), "+f"(c[3])
        : "r"(a[0]), "r"(a[1]), "r"(a[2]), "r"(a[3]), "r"(b[0]), "r"(b[1]));
}
__device__ __forceinline__ void ldsm4(uint32_t* r, uint32_t addr) {
    asm volatile("ldmatrix.sync.aligned.m8n8.x4.shared.b16 {%0,%1,%2,%3}, [%4];"
                 : "=r"(r[0]), "=r"(r[1]), "=r"(r[2]), "=r"(r[3]) : "r"(addr));
}
__device__ __forceinline__ void cp16(uint32_t s, const void* g) {
    asm volatile("cp.async.cg.shared.global [%0], [%1], 16;" :: "r"(s), "l"(g) : "memory");
}
__device__ __forceinline__ void cp_commit() {
    asm volatile("cp.async.commit_group;" ::: "memory");
}
__device__ __forceinline__ void cp_wait2() {
    asm volatile("cp.async.wait_group 2;" ::: "memory");
}

// ===================== main GEMM loop =====================
// 8 warps, warp tile 64x64, fragment double-buffered over kk.
// One __syncthreads per k-step; stage written at iter s is (s-1)%4 (safe).
__device__ __forceinline__ void gemm_main(
    const float* __restrict__ pA, const float* __restrict__ pB,
    size_t lda, int NK, uint32_t su, float acc[4][8][4])
{
    const int tid  = threadIdx.x;
    const int lane = tid & 31;
    const int w    = tid >> 5;
    const int wm   = (w & 1) * 64;    // 2 m-warps
    const int wn   = (w >> 1) * 64;   // 4 n-warps

    // -- cp.async addressing: 8 threads per 128B row --
    const int rr = tid >> 3;            // 0..31 (base row, +32 per rep)
    const int q  = tid & 7;             // 16B quad in row
    const float*  asrc = pA + (size_t)rr * lda + q * 4;
    const float*  bsrc = pB + (size_t)rr * lda + q * 4;
    const uint32_t adst = su + (rr * ASTR + q * 4) * 4;
    const uint32_t bdst = su + ABYTES + (rr * BSTR + q * 4) * 4;
    const size_t gstep = (size_t)lda * 32;       // 32 rows, in floats

    auto load_stage = [&](int s, int st) {
        const uint32_t o = st * STG;
        const size_t ko = (size_t)s * BK;
        #pragma unroll
        for (int i = 0; i < 4; i++)                       // A: 128 rows
            cp16(adst + o + i * 32 * ASTR * 4, asrc + ko + i * gstep);
        #pragma unroll
        for (int i = 0; i < 8; i++)                       // B: 256 rows
            cp16(bdst + o + i * 32 * BSTR * 4, bsrc + ko + i * gstep);
    };

    // -- ldmatrix per-lane offsets (bytes, rel. to stage base) --
    const int la = lane & 7, lb = (lane >> 3) & 1, lc = (lane >> 4) & 1;
    const uint32_t aoff0 = ((wm + la + lb * 8) * ASTR + lc * 4) * 4;
    uint32_t boff[4];
    #pragma unroll
    for (int p = 0; p < 4; p++)
        boff[p] = ABYTES + ((wn + p * 16 + la + lc * 8) * BSTR + lb * 4) * 4;

    // fragment double buffers
    uint32_t afb[2][4][4], bfb[2][4][4];

    auto ldfrag = [&](int buf, uint32_t sa, int kk) {
        #pragma unroll
        for (int mt = 0; mt < 4; mt++)
            ldsm4(afb[buf][mt], sa + aoff0 + mt * (16 * ASTR * 4) + kk * 32);
        #pragma unroll
        for (int p = 0; p < 4; p++)
            ldsm4(bfb[buf][p], sa + boff[p] + kk * 32);
    };
    auto compute = [&](int buf) {
        #pragma unroll
        for (int mt = 0; mt < 4; mt++)
            #pragma unroll
            for (int nt = 0; nt < 8; nt++)
                mma8(acc[mt][nt], afb[buf][mt], &bfb[buf][nt >> 1][(nt & 1) * 2]);
    };

    // -- prologue: stages 0,1,2 --
    #pragma unroll
    for (int s = 0; s < NSTG - 1; ++s) {
        load_stage(s, s);
        cp_commit();
    }

    #pragma unroll 1
    for (int s = 0; s < NK; ++s) {
        cp_wait2();            // oldest outstanding stage (s) resident
        __syncthreads();       // all warps done reading stage (s-1)%4

        if (s + NSTG - 1 < NK)
            load_stage(s + NSTG - 1, (s + NSTG - 1) & 3);
        cp_commit();

        const uint32_t sa = su + (s & 3) * STG;
        ldfrag(0, sa, 0);
        #pragma unroll
        for (int kk = 0; kk < 4; ++kk) {
            if (kk < 3) ldfrag((kk + 1) & 1, sa, kk + 1);
            compute(kk & 1);
        }
    }
}

// ===================== GEMM1: xc @ W1t -> GLU -> g_fw =====================
__global__ __launch_bounds__(NTHR, 1) void k_gemm1(
    const float* __restrict__ b1, const float* __restrict__ rw)
{
    extern __shared__ char smraw[];
    const uint32_t su = smem_u32(smraw);
    const int m0 = blockIdx.x * BM;
    const int n0 = blockIdx.y * BN;
    const int e  = blockIdx.z;

    float acc[4][8][4];
    #pragma unroll
    for (int a = 0; a < 4; a++)
        #pragma unroll
        for (int b = 0; b < 8; b++)
            #pragma unroll
            for (int q = 0; q < 4; q++) acc[a][b][q] = 0.f;

    gemm_main(g_xc + (size_t)m0 * HID,
              g_w1t + ((size_t)e * N1 + n0) * HID,
              HID, HID / BK, su, acc);

    const int lane = threadIdx.x & 31, w = threadIdx.x >> 5;
    const int wm = (w & 1) * 64, wn = (w >> 1) * 64;
    uint32_t* fw = (uint32_t*)g_fw;
    #pragma unroll
    for (int mt = 0; mt < 4; mt++) {
        const int r = m0 + wm + mt * 16 + (lane >> 2);
        const float rwa = rw[r * EXP + e];
        const float rwb = rw[(r + 8) * EXP + e];
        #pragma unroll
        for (int nt = 0; nt < 8; nt++) {
            const int cn = n0 + wn + nt * 8 + (lane & 3) * 2;  // even = gate
            const float bg = b1[e * N1 + cn];
            const float bu = b1[e * N1 + cn + 1];
            const int d = cn >> 1;
            {
                float g = fminf(acc[mt][nt][0] + bg, 7.f);
                float u = fminf(fmaxf(acc[mt][nt][1] + bu, -7.f), 7.f);
                float glu = g / (1.f + __expf(-1.702f * g));
                fw[(size_t)r * K2P + e * 2048 + d] = f2tf((u + 1.f) * glu * rwa);
            }
            {
                float g = fminf(acc[mt][nt][2] + bg, 7.f);
                float u = fminf(fmaxf(acc[mt][nt][3] + bu, -7.f), 7.f);
                float glu = g / (1.f + __expf(-1.702f * g));
                fw[(size_t)(r + 8) * K2P + e * 2048 + d] = f2tf((u + 1.f) * glu * rwb);
            }
        }
    }
}

// ===================== GEMM2: g_fw @ W2t (bias in K-tail) -> out =====================
__global__ __launch_bounds__(NTHR, 1) void k_gemm2(float* __restrict__ out)
{
    extern __shared__ char smraw[];
    const uint32_t su = smem_u32(smraw);
    const int m0 = blockIdx.x * BM;
    const int n0 = blockIdx.y * BN;

    float acc[4][8][4];
    #pragma unroll
    for (int a = 0; a < 4; a++)
        #pragma unroll
        for (int b = 0; b < 8; b++)
            #pragma unroll
            for (int q = 0; q < 4; q++) acc[a][b][q] = 0.f;

    gemm_main(g_fw + (size_t)m0 * K2P,
              g_w2t + (size_t)n0 * K2P,
              K2P, K2P / BK, su, acc);     // 513 k-steps

    const int lane = threadIdx.x & 31, w = threadIdx.x >> 5;
    const int wm = (w & 1) * 64, wn = (w >> 1) * 64;
    #pragma unroll
    for (int mt = 0; mt < 4; mt++) {
        const int r = m0 + wm + mt * 16 + (lane >> 2);
        #pragma unroll
        for (int nt = 0; nt < 8; nt++) {
            const int cn = n0 + wn + nt * 8 + (lane & 3) * 2;
            *(float2*)&out[(size_t)r * HID + cn] =
                make_float2(acc[mt][nt][0], acc[mt][nt][1]);
            *(float2*)&out[(size_t)(r + 8) * HID + cn] =
                make_float2(acc[mt][nt][2], acc[mt][nt][3]);
        }
    }
}

// ===================== prepass =====================
// W1[e][h][n] -> g_w1t[e][n][h]  (tf32-rounded)
__global__ void k_tr1(const float* __restrict__ w1) {
    __shared__ float s[32][33];
    const int tx = threadIdx.x, ty = threadIdx.y;
    const int n0 = blockIdx.x * 32, h0 = blockIdx.y * 32, e = blockIdx.z;
    #pragma unroll
    for (int i = 0; i < 4; i++)
        s[ty + 8 * i][tx] = w1[((size_t)e * HID + h0 + ty + 8 * i) * N1 + n0 + tx];
    __syncthreads();
    #pragma unroll
    for (int i = 0; i < 4; i++)
        ((uint32_t*)g_w1t)[((size_t)e * N1 + n0 + ty + 8 * i) * HID + h0 + tx] =
            f2tf(s[tx][ty + 8 * i]);
}

// W2flat[k][h] -> g_w2t[h][k]  (tf32-rounded, stride K2P)
__global__ void k_tr2(const float* __restrict__ w2) {
    __shared__ float s[32][33];
    const int tx = threadIdx.x, ty = threadIdx.y;
    const int h0 = blockIdx.x * 32, k0 = blockIdx.y * 32;
    #pragma unroll
    for (int i = 0; i < 4; i++)
        s[ty + 8 * i][tx] = w2[(size_t)(k0 + ty + 8 * i) * HID + h0 + tx];
    __syncthreads();
    #pragma unroll
    for (int i = 0; i < 4; i++)
        ((uint32_t*)g_w2t)[(size_t)(h0 + ty + 8 * i) * K2P + k0 + tx] =
            f2tf(s[tx][ty + 8 * i]);
}

// fused: x -> tf32 g_xc  AND  K-tail init for g_fw / g_w2t
__global__ void k_misc(const float* __restrict__ x, const float* __restrict__ rw,
                       const float* __restrict__ b2) {
    const int b = blockIdx.x;
    if (b < 2048) {
        const size_t base = (size_t)b * 2048 + threadIdx.x * 8;
        #pragma unroll
        for (int i = 0; i < 2; i++) {
            float4 v = *(const float4*)(x + base + i * 4);
            *(uint4*)((uint32_t*)g_xc + base + i * 4) =
                make_uint4(f2tf(v.x), f2tf(v.y), f2tf(v.z), f2tf(v.w));
        }
    } else {
        const int row = b - 2048;          // 0..2047
        const int t = threadIdx.x;
        if (t < 32)
            ((uint32_t*)g_fw)[(size_t)row * K2P + K2 + t] =
                (t < 8) ? f2tf(rw[row * EXP + t]) : 0u;
        else if (t < 64) {
            const int j = t - 32;
            ((uint32_t*)g_w2t)[(size_t)row * K2P + K2 + j] =
                (j < 8) ? f2tf(b2[j * HID + row]) : 0u;
        }
    }
}

// ===================== launch =====================
extern "C" void kernel_launch(void* const* d_in, const int* in_sizes, int n_in,
                              void* d_out, int out_size) {
    const float* x  = (const float*)d_in[0];
    const float* rw = (const float*)d_in[1];
    const float* w1 = (const float*)d_in[2];
    const float* b1 = (const float*)d_in[3];
    const float* w2 = (const float*)d_in[4];
    const float* b2 = (const float*)d_in[5];
    float* out = (float*)d_out;

    cudaFuncSetAttribute(k_gemm1, cudaFuncAttributeMaxDynamicSharedMemorySize, SMEM_SZ);
    cudaFuncSetAttribute(k_gemm2, cudaFuncAttributeMaxDynamicSharedMemorySize, SMEM_SZ);

    k_tr1 <<<dim3(N1 / 32, HID / 32, EXP), dim3(32, 8)>>>(w1);
    k_tr2 <<<dim3(HID / 32, K2 / 32), dim3(32, 8)>>>(w2);
    k_misc<<<4096, 256>>>(x, rw, b2);

    k_gemm1<<<dim3(T_TOK / BM, N1 / BN, EXP), NTHR, SMEM_SZ>>>(b1, rw);
    k_gemm2<<<dim3(T_TOK / BM, HID / BN), NTHR, SMEM_SZ>>>(out);
}

// round 13
// speedup vs baseline: 1.0899x; 1.0899x over previous
#include <cuda_runtime.h>
#include <cstdint>

// ---- problem dims ----
#define T_TOK 2048
#define HID   2048
#define EXP   8
#define N1    4096
#define K2    16384
#define K2P   16416   // K2 + 32: bias folded into K (cols 16384..16391 = rw / down_b)

// ---- tiling ----
constexpr int BM = 128, BN = 128, BK = 32;
constexpr int NTHR = 256;             // 8 warps: 4 (m) x 2 (n), warp tile 32x64
constexpr int NSTG = 3;
constexpr int ASTR = 36, BSTR = 36;   // words/row (32 data + 4 pad): conflict-free
constexpr int ABYTES = BM * ASTR * 4;       // 18432
constexpr int BBYTES = BN * BSTR * 4;       // 18432
constexpr int STG = ABYTES + BBYTES;        // 36864
constexpr int SMEM_SZ = NSTG * STG;         // 110592  -> 2 CTAs / SM

// ---- scratch (device globals; allocation forbidden) ----
__device__ __align__(1024) float g_xc [(size_t)T_TOK * HID];      // tf32-rounded x
__device__ __align__(1024) float g_w1t[(size_t)EXP * N1 * HID];   // [e][n][h]
__device__ __align__(1024) float g_w2t[(size_t)HID * K2P];        // [h][k] (+bias tail)
__device__ __align__(1024) float g_fw [(size_t)T_TOK * K2P];      // rw-scaled GLU (+rw tail)

// ===================== helpers =====================
__device__ __forceinline__ uint32_t smem_u32(const void* p) {
    uint32_t a;
    asm("{ .reg .u64 t; cvta.to.shared.u64 t, %1; cvt.u32.u64 %0, t; }" : "=r"(a) : "l"(p));
    return a;
}
__device__ __forceinline__ uint32_t f2tf(float f) {
    uint32_t u; asm("cvt.rna.tf32.f32 %0, %1;" : "=r"(u) : "f"(f)); return u;
}
__device__ __forceinline__ void mma8(float* c, const uint32_t* a, const uint32_t* b) {
    asm volatile(
        "mma.sync.aligned.m16n8k8.row.col.f32.tf32.tf32.f32 "
        "{%0,%1,%2,%3}, {%4,%5,%6,%7}, {%8,%9}, {%0,%1,%2,%3};"
        : "+f"(c[0]), "+f"(c[1]), "+f"(c[2]), "+f"(c[3])
        : "r"(a[0]), "r"(a[1]), "r"(a[2]), "r"(a[3]), "r"(b[0]), "r"(b[1]));
}
__device__ __forceinline__ void ldsm4(uint32_t* r, uint32_t addr) {
    asm volatile("ldmatrix.sync.aligned.m8n8.x4.shared.b16 {%0,%1,%2,%3}, [%4];"
                 : "=r"(r[0]), "=r"(r[1]), "=r"(r[2]), "=r"(r[3]) : "r"(addr));
}
__device__ __forceinline__ void cp16(uint32_t s, const void* g) {
    asm volatile("cp.async.cg.shared.global [%0], [%1], 16;" :: "r"(s), "l"(g) : "memory");
}
__device__ __forceinline__ void cp_commit() {
    asm volatile("cp.async.commit_group;" ::: "memory");
}
__device__ __forceinline__ void cp_wait1() {
    asm volatile("cp.async.wait_group 1;" ::: "memory");
}

// ===================== main GEMM loop =====================
// 8 warps, warp tile 32x64. One __syncthreads per k-step; at iter s we write
// stage (s+2)%3 == (s-1)%3, whose reads finished before this barrier -> safe.
__device__ __forceinline__ void gemm_main(
    const float* __restrict__ pA, const float* __restrict__ pB,
    size_t lda, int NK, uint32_t su, float acc[2][8][4])
{
    const int tid  = threadIdx.x;
    const int lane = tid & 31;
    const int w    = tid >> 5;
    const int wm   = (w & 3) * 32;    // 4 m-warps
    const int wn   = (w >> 2) * 64;   // 2 n-warps

    // -- cp.async addressing: 8 threads per 128B row --
    const int rr = tid >> 3;            // 0..31 (base row, +32 per rep)
    const int q  = tid & 7;             // 16B quad in row
    const float*  asrc = pA + (size_t)rr * lda + q * 4;
    const float*  bsrc = pB + (size_t)rr * lda + q * 4;
    const uint32_t adst = su + (rr * ASTR + q * 4) * 4;
    const uint32_t bdst = su + ABYTES + (rr * BSTR + q * 4) * 4;
    const size_t gstep = (size_t)lda * 32;       // 32 rows, in floats

    auto load_stage = [&](int s, int st) {
        const uint32_t o = st * STG;
        const size_t ko = (size_t)s * BK;
        #pragma unroll
        for (int i = 0; i < 4; i++)                       // A: 128 rows
            cp16(adst + o + i * 32 * ASTR * 4, asrc + ko + i * gstep);
        #pragma unroll
        for (int i = 0; i < 4; i++)                       // B: 128 rows
            cp16(bdst + o + i * 32 * BSTR * 4, bsrc + ko + i * gstep);
    };

    // -- ldmatrix per-lane offsets (bytes, rel. to stage base) --
    const int la = lane & 7, lb = (lane >> 3) & 1, lc = (lane >> 4) & 1;
    const uint32_t aoff0 = ((wm + la + lb * 8) * ASTR + lc * 4) * 4;
    const uint32_t aoff1 = aoff0 + 16 * ASTR * 4;
    uint32_t boff[4];
    #pragma unroll
    for (int p = 0; p < 4; p++)
        boff[p] = ABYTES + ((wn + p * 16 + la + lc * 8) * BSTR + lb * 4) * 4;

    // -- prologue: stages 0,1 --
    load_stage(0, 0); cp_commit();
    load_stage(1, 1); cp_commit();

    int st = 0;                      // current compute stage
    int wst = 2;                     // stage slot to write next
    #pragma unroll 1
    for (int s = 0; s < NK; ++s) {
        cp_wait1();            // oldest outstanding stage (s) resident
        __syncthreads();       // all warps done reading stage (s-1)%3

        if (s + 2 < NK)
            load_stage(s + 2, wst);
        cp_commit();

        const uint32_t sa = su + st * STG;
        #pragma unroll
        for (int kk = 0; kk < 4; ++kk) {
            uint32_t af[2][4], bf[4][4];
            ldsm4(af[0], sa + aoff0 + kk * 32);
            ldsm4(af[1], sa + aoff1 + kk * 32);
            #pragma unroll
            for (int p = 0; p < 4; p++) ldsm4(bf[p], sa + boff[p] + kk * 32);
            #pragma unroll
            for (int mt = 0; mt < 2; mt++)
                #pragma unroll
                for (int nt = 0; nt < 8; nt++)
                    mma8(acc[mt][nt], af[mt], &bf[nt >> 1][(nt & 1) * 2]);
        }
        if (++st == NSTG) st = 0;
        if (++wst == NSTG) wst = 0;
    }
}

// ===================== GEMM1: xc @ W1t -> GLU -> g_fw =====================
__global__ __launch_bounds__(NTHR, 2) void k_gemm1(
    const float* __restrict__ b1, const float* __restrict__ rw)
{
    extern __shared__ char smraw[];
    const uint32_t su = smem_u32(smraw);
    const int m0 = blockIdx.x * BM;
    const int n0 = blockIdx.y * BN;
    const int e  = blockIdx.z;

    float acc[2][8][4];
    #pragma unroll
    for (int a = 0; a < 2; a++)
        #pragma unroll
        for (int b = 0; b < 8; b++)
            #pragma unroll
            for (int q = 0; q < 4; q++) acc[a][b][q] = 0.f;

    gemm_main(g_xc + (size_t)m0 * HID,
              g_w1t + ((size_t)e * N1 + n0) * HID,
              HID, HID / BK, su, acc);

    const int lane = threadIdx.x & 31, w = threadIdx.x >> 5;
    const int wm = (w & 3) * 32, wn = (w >> 2) * 64;
    uint32_t* fw = (uint32_t*)g_fw;
    #pragma unroll
    for (int mt = 0; mt < 2; mt++) {
        const int r = m0 + wm + mt * 16 + (lane >> 2);
        const float rwa = rw[r * EXP + e];
        const float rwb = rw[(r + 8) * EXP + e];
        #pragma unroll
        for (int nt = 0; nt < 8; nt++) {
            const int cn = n0 + wn + nt * 8 + (lane & 3) * 2;  // even = gate
            const float bg = b1[e * N1 + cn];
            const float bu = b1[e * N1 + cn + 1];
            const int d = cn >> 1;
            {
                float g = fminf(acc[mt][nt][0] + bg, 7.f);
                float u = fminf(fmaxf(acc[mt][nt][1] + bu, -7.f), 7.f);
                float glu = g / (1.f + __expf(-1.702f * g));
                fw[(size_t)r * K2P + e * 2048 + d] = f2tf((u + 1.f) * glu * rwa);
            }
            {
                float g = fminf(acc[mt][nt][2] + bg, 7.f);
                float u = fminf(fmaxf(acc[mt][nt][3] + bu, -7.f), 7.f);
                float glu = g / (1.f + __expf(-1.702f * g));
                fw[(size_t)(r + 8) * K2P + e * 2048 + d] = f2tf((u + 1.f) * glu * rwb);
            }
        }
    }
}

// ===================== GEMM2: g_fw @ W2t (bias in K-tail) -> out =====================
__global__ __launch_bounds__(NTHR, 2) void k_gemm2(float* __restrict__ out)
{
    extern __shared__ char smraw[];
    const uint32_t su = smem_u32(smraw);
    const int m0 = blockIdx.x * BM;
    const int n0 = blockIdx.y * BN;

    float acc[2][8][4];
    #pragma unroll
    for (int a = 0; a < 2; a++)
        #pragma unroll
        for (int b = 0; b < 8; b++)
            #pragma unroll
            for (int q = 0; q < 4; q++) acc[a][b][q] = 0.f;

    gemm_main(g_fw + (size_t)m0 * K2P,
              g_w2t + (size_t)n0 * K2P,
              K2P, K2P / BK, su, acc);     // 513 k-steps

    const int lane = threadIdx.x & 31, w = threadIdx.x >> 5;
    const int wm = (w & 3) * 32, wn = (w >> 2) * 64;
    #pragma unroll
    for (int mt = 0; mt < 2; mt++) {
        const int r = m0 + wm + mt * 16 + (lane >> 2);
        #pragma unroll
        for (int nt = 0; nt < 8; nt++) {
            const int cn = n0 + wn + nt * 8 + (lane & 3) * 2;
            *(float2*)&out[(size_t)r * HID + cn] =
                make_float2(acc[mt][nt][0], acc[mt][nt][1]);
            *(float2*)&out[(size_t)(r + 8) * HID + cn] =
                make_float2(acc[mt][nt][2], acc[mt][nt][3]);
        }
    }
}

// ===================== prepass =====================
// W1[e][h][n] -> g_w1t[e][n][h]  (tf32-rounded)
__global__ void k_tr1(const float* __restrict__ w1) {
    __shared__ float s[32][33];
    const int tx = threadIdx.x, ty = threadIdx.y;
    const int n0 = blockIdx.x * 32, h0 = blockIdx.y * 32, e = blockIdx.z;
    #pragma unroll
    for (int i = 0; i < 4; i++)
        s[ty + 8 * i][tx] = w1[((size_t)e * HID + h0 + ty + 8 * i) * N1 + n0 + tx];
    __syncthreads();
    #pragma unroll
    for (int i = 0; i < 4; i++)
        ((uint32_t*)g_w1t)[((size_t)e * N1 + n0 + ty + 8 * i) * HID + h0 + tx] =
            f2tf(s[tx][ty + 8 * i]);
}

// W2flat[k][h] -> g_w2t[h][k]  (tf32-rounded, stride K2P)
__global__ void k_tr2(const float* __restrict__ w2) {
    __shared__ float s[32][33];
    const int tx = threadIdx.x, ty = threadIdx.y;
    const int h0 = blockIdx.x * 32, k0 = blockIdx.y * 32;
    #pragma unroll
    for (int i = 0; i < 4; i++)
        s[ty + 8 * i][tx] = w2[(size_t)(k0 + ty + 8 * i) * HID + h0 + tx];
    __syncthreads();
    #pragma unroll
    for (int i = 0; i < 4; i++)
        ((uint32_t*)g_w2t)[(size_t)(h0 + ty + 8 * i) * K2P + k0 + tx] =
            f2tf(s[tx][ty + 8 * i]);
}

// fused: x -> tf32 g_xc  AND  K-tail init for g_fw / g_w2t
__global__ void k_misc(const float* __restrict__ x, const float* __restrict__ rw,
                       const float* __restrict__ b2) {
    const int b = blockIdx.x;
    if (b < 2048) {
        const size_t base = (size_t)b * 2048 + threadIdx.x * 8;
        #pragma unroll
        for (int i = 0; i < 2; i++) {
            float4 v = *(const float4*)(x + base + i * 4);
            *(uint4*)((uint32_t*)g_xc + base + i * 4) =
                make_uint4(f2tf(v.x), f2tf(v.y), f2tf(v.z), f2tf(v.w));
        }
    } else {
        const int row = b - 2048;          // 0..2047
        const int t = threadIdx.x;
        if (t < 32)
            ((uint32_t*)g_fw)[(size_t)row * K2P + K2 + t] =
                (t < 8) ? f2tf(rw[row * EXP + t]) : 0u;
        else if (t < 64) {
            const int j = t - 32;
            ((uint32_t*)g_w2t)[(size_t)row * K2P + K2 + j] =
                (j < 8) ? f2tf(b2[j * HID + row]) : 0u;
        }
    }
}

// ===================== launch =====================
extern "C" void kernel_launch(void* const* d_in, const int* in_sizes, int n_in,
                              void* d_out, int out_size) {
    const float* x  = (const float*)d_in[0];
    const float* rw = (const float*)d_in[1];
    const float* w1 = (const float*)d_in[2];
    const float* b1 = (const float*)d_in[3];
    const float* w2 = (const float*)d_in[4];
    const float* b2 = (const float*)d_in[5];
    float* out = (float*)d_out;

    cudaFuncSetAttribute(k_gemm1, cudaFuncAttributeMaxDynamicSharedMemorySize, SMEM_SZ);
    cudaFuncSetAttribute(k_gemm2, cudaFuncAttributeMaxDynamicSharedMemorySize, SMEM_SZ);

    k_tr1 <<<dim3(N1 / 32, HID / 32, EXP), dim3(32, 8)>>>(w1);
    k_tr2 <<<dim3(HID / 32, K2 / 32), dim3(32, 8)>>>(w2);
    k_misc<<<4096, 256>>>(x, rw, b2);

    k_gemm1<<<dim3(T_TOK / BM, N1 / BN, EXP), NTHR, SMEM_SZ>>>(b1, rw);
    k_gemm2<<<dim3(T_TOK / BM, HID / BN), NTHR, SMEM_SZ>>>(out);
}

// round 14
// speedup vs baseline: 1.1057x; 1.0145x over previous
#include <cuda_runtime.h>
#include <cstdint>

// ---- problem dims ----
#define T_TOK 2048
#define HID   2048
#define EXP   8
#define N1    4096
#define K2    16384
#define K2P   16416   // K2 + 32: bias folded into K (cols 16384..16391 = rw / down_b)

// ---- tiling ----
constexpr int BM = 128, BN = 128, BK = 32;
constexpr int NTHR = 256;             // 8 warps: 4 (m) x 2 (n), warp tile 32x64
constexpr int NSTG = 3;
constexpr int ASTR = 36, BSTR = 36;   // words/row (32 data + 4 pad): conflict-free ldsm
constexpr int ABYTES = BM * ASTR * 4;       // 18432
constexpr int BBYTES = BN * BSTR * 4;       // 18432
constexpr int STG = ABYTES + BBYTES;        // 36864
constexpr int SMEM_SZ = NSTG * STG;         // 110592  -> 2 CTAs / SM

// ---- scratch (device globals; allocation forbidden) ----
__device__ __align__(1024) float g_xc [(size_t)T_TOK * HID];      // tf32-rounded x
__device__ __align__(1024) float g_w1t[(size_t)EXP * N1 * HID];   // [e][n][h]
__device__ __align__(1024) float g_w2t[(size_t)HID * K2P];        // [h][k] (+bias tail)
__device__ __align__(1024) float g_fw [(size_t)T_TOK * K2P];      // rw-scaled GLU (+rw tail)

// ===================== helpers =====================
__device__ __forceinline__ uint32_t smem_u32(const void* p) {
    uint32_t a;
    asm("{ .reg .u64 t; cvta.to.shared.u64 t, %1; cvt.u32.u64 %0, t; }" : "=r"(a) : "l"(p));
    return a;
}
__device__ __forceinline__ uint32_t f2tf(float f) {
    uint32_t u; asm("cvt.rna.tf32.f32 %0, %1;" : "=r"(u) : "f"(f)); return u;
}
__device__ __forceinline__ void mma8(float* c, const uint32_t* a, const uint32_t* b) {
    asm volatile(
        "mma.sync.aligned.m16n8k8.row.col.f32.tf32.tf32.f32 "
        "{%0,%1,%2,%3}, {%4,%5,%6,%7}, {%8,%9}, {%0,%1,%2,%3};"
        : "+f"(c[0]), "+f"(c[1]), "+f"(c[2]), "+f"(c[3])
        : "r"(a[0]), "r"(a[1]), "r"(a[2]), "r"(a[3]), "r"(b[0]), "r"(b[1]));
}
__device__ __forceinline__ void ldsm4(uint32_t* r, uint32_t addr) {
    asm volatile("ldmatrix.sync.aligned.m8n8.x4.shared.b16 {%0,%1,%2,%3}, [%4];"
                 : "=r"(r[0]), "=r"(r[1]), "=r"(r[2]), "=r"(r[3]) : "r"(addr));
}
__device__ __forceinline__ void cp16(uint32_t s, const void* g) {
    asm volatile("cp.async.cg.shared.global [%0], [%1], 16;" :: "r"(s), "l"(g) : "memory");
}
__device__ __forceinline__ void cp_commit() {
    asm volatile("cp.async.commit_group;" ::: "memory");
}
__device__ __forceinline__ void cp_wait1() {
    asm volatile("cp.async.wait_group 1;" ::: "memory");
}

// ===================== main GEMM loop =====================
// 8 warps, warp tile 32x64, B fragments double-buffered across kk.
// One __syncthreads per k-step; at iter s we write stage (s+2)%3 == (s-1)%3,
// whose reads completed before this barrier -> safe.
__device__ __forceinline__ void gemm_main(
    const float* __restrict__ pA, const float* __restrict__ pB,
    size_t lda, int NK, uint32_t su, float acc[2][8][4])
{
    const int tid  = threadIdx.x;
    const int lane = tid & 31;
    const int w    = tid >> 5;
    const int wm   = (w & 3) * 32;    // 4 m-warps
    const int wn   = (w >> 2) * 64;   // 2 n-warps

    // -- cp.async addressing: 8 threads per 128B row --
    const int rr = tid >> 3;            // 0..31 (base row, +32 per rep)
    const int q  = tid & 7;             // 16B quad in row
    const float*  asrc = pA + (size_t)rr * lda + q * 4;
    const float*  bsrc = pB + (size_t)rr * lda + q * 4;
    const uint32_t adst = su + (rr * ASTR + q * 4) * 4;
    const uint32_t bdst = su + ABYTES + (rr * BSTR + q * 4) * 4;
    const size_t gstep = (size_t)lda * 32;       // 32 rows, in floats

    auto load_stage = [&](int s, int st) {
        const uint32_t o = st * STG;
        const size_t ko = (size_t)s * BK;
        #pragma unroll
        for (int i = 0; i < 4; i++)                       // A: 128 rows
            cp16(adst + o + i * 32 * ASTR * 4, asrc + ko + i * gstep);
        #pragma unroll
        for (int i = 0; i < 4; i++)                       // B: 128 rows
            cp16(bdst + o + i * 32 * BSTR * 4, bsrc + ko + i * gstep);
    };

    // -- ldmatrix per-lane offsets (bytes, rel. to stage base) --
    const int la = lane & 7, lb = (lane >> 3) & 1, lc = (lane >> 4) & 1;
    const uint32_t aoff0 = ((wm + la + lb * 8) * ASTR + lc * 4) * 4;
    const uint32_t aoff1 = aoff0 + 16 * ASTR * 4;
    uint32_t boff[4];
    #pragma unroll
    for (int p = 0; p < 4; p++)
        boff[p] = ABYTES + ((wn + p * 16 + la + lc * 8) * BSTR + lb * 4) * 4;

    // B fragment double buffer (A loaded per-kk)
    uint32_t bf[2][4][4];
    auto ldbf = [&](int buf, uint32_t sa, int kk) {
        #pragma unroll
        for (int p = 0; p < 4; p++)
            ldsm4(bf[buf][p], sa + boff[p] + kk * 32);
    };

    // -- prologue: stages 0,1 --
    load_stage(0, 0); cp_commit();
    load_stage(1, 1); cp_commit();

    int st = 0;                      // current compute stage
    int wst = 2;                     // stage slot to write next
    #pragma unroll 1
    for (int s = 0; s < NK; ++s) {
        cp_wait1();            // oldest outstanding stage (s) resident
        __syncthreads();       // all warps done reading stage (s-1)%3

        if (s + 2 < NK)
            load_stage(s + 2, wst);
        cp_commit();

        const uint32_t sa = su + st * STG;
        ldbf(0, sa, 0);
        #pragma unroll
        for (int kk = 0; kk < 4; ++kk) {
            uint32_t af[2][4];
            ldsm4(af[0], sa + aoff0 + kk * 32);
            ldsm4(af[1], sa + aoff1 + kk * 32);
            if (kk < 3) ldbf((kk + 1) & 1, sa, kk + 1);
            #pragma unroll
            for (int mt = 0; mt < 2; mt++)
                #pragma unroll
                for (int nt = 0; nt < 8; nt++)
                    mma8(acc[mt][nt], af[mt], &bf[kk & 1][nt >> 1][(nt & 1) * 2]);
        }
        if (++st == NSTG) st = 0;
        if (++wst == NSTG) wst = 0;
    }
}

// ===================== GEMM1: xc @ W1t -> GLU -> g_fw =====================
__global__ __launch_bounds__(NTHR, 2) void k_gemm1(
    const float* __restrict__ b1, const float* __restrict__ rw)
{
    extern __shared__ char smraw[];
    const uint32_t su = smem_u32(smraw);
    const int m0 = blockIdx.x * BM;
    const int n0 = blockIdx.y * BN;
    const int e  = blockIdx.z;

    float acc[2][8][4];
    #pragma unroll
    for (int a = 0; a < 2; a++)
        #pragma unroll
        for (int b = 0; b < 8; b++)
            #pragma unroll
            for (int q = 0; q < 4; q++) acc[a][b][q] = 0.f;

    gemm_main(g_xc + (size_t)m0 * HID,
              g_w1t + ((size_t)e * N1 + n0) * HID,
              HID, HID / BK, su, acc);

    const int lane = threadIdx.x & 31, w = threadIdx.x >> 5;
    const int wm = (w & 3) * 32, wn = (w >> 2) * 64;
    uint32_t* fw = (uint32_t*)g_fw;
    #pragma unroll
    for (int mt = 0; mt < 2; mt++) {
        const int r = m0 + wm + mt * 16 + (lane >> 2);
        const float rwa = rw[r * EXP + e];
        const float rwb = rw[(r + 8) * EXP + e];
        #pragma unroll
        for (int nt = 0; nt < 8; nt++) {
            const int cn = n0 + wn + nt * 8 + (lane & 3) * 2;  // even = gate
            const float bg = b1[e * N1 + cn];
            const float bu = b1[e * N1 + cn + 1];
            const int d = cn >> 1;
            {
                float g = fminf(acc[mt][nt][0] + bg, 7.f);
                float u = fminf(fmaxf(acc[mt][nt][1] + bu, -7.f), 7.f);
                float glu = g / (1.f + __expf(-1.702f * g));
                fw[(size_t)r * K2P + e * 2048 + d] = f2tf((u + 1.f) * glu * rwa);
            }
            {
                float g = fminf(acc[mt][nt][2] + bg, 7.f);
                float u = fminf(fmaxf(acc[mt][nt][3] + bu, -7.f), 7.f);
                float glu = g / (1.f + __expf(-1.702f * g));
                fw[(size_t)(r + 8) * K2P + e * 2048 + d] = f2tf((u + 1.f) * glu * rwb);
            }
        }
    }
}

// ===================== GEMM2: g_fw @ W2t (bias in K-tail) -> out =====================
__global__ __launch_bounds__(NTHR, 2) void k_gemm2(float* __restrict__ out)
{
    extern __shared__ char smraw[];
    const uint32_t su = smem_u32(smraw);
    const int m0 = blockIdx.x * BM;
    const int n0 = blockIdx.y * BN;

    float acc[2][8][4];
    #pragma unroll
    for (int a = 0; a < 2; a++)
        #pragma unroll
        for (int b = 0; b < 8; b++)
            #pragma unroll
            for (int q = 0; q < 4; q++) acc[a][b][q] = 0.f;

    gemm_main(g_fw + (size_t)m0 * K2P,
              g_w2t + (size_t)n0 * K2P,
              K2P, K2P / BK, su, acc);     // 513 k-steps

    const int lane = threadIdx.x & 31, w = threadIdx.x >> 5;
    const int wm = (w & 3) * 32, wn = (w >> 2) * 64;
    #pragma unroll
    for (int mt = 0; mt < 2; mt++) {
        const int r = m0 + wm + mt * 16 + (lane >> 2);
        #pragma unroll
        for (int nt = 0; nt < 8; nt++) {
            const int cn = n0 + wn + nt * 8 + (lane & 3) * 2;
            *(float2*)&out[(size_t)r * HID + cn] =
                make_float2(acc[mt][nt][0], acc[mt][nt][1]);
            *(float2*)&out[(size_t)(r + 8) * HID + cn] =
                make_float2(acc[mt][nt][2], acc[mt][nt][3]);
        }
    }
}

// ===================== prepass =====================
// W1[e][h][n] -> g_w1t[e][n][h]  (tf32-rounded)
__global__ void k_tr1(const float* __restrict__ w1) {
    __shared__ float s[32][33];
    const int tx = threadIdx.x, ty = threadIdx.y;
    const int n0 = blockIdx.x * 32, h0 = blockIdx.y * 32, e = blockIdx.z;
    #pragma unroll
    for (int i = 0; i < 4; i++)
        s[ty + 8 * i][tx] = w1[((size_t)e * HID + h0 + ty + 8 * i) * N1 + n0 + tx];
    __syncthreads();
    #pragma unroll
    for (int i = 0; i < 4; i++)
        ((uint32_t*)g_w1t)[((size_t)e * N1 + n0 + ty + 8 * i) * HID + h0 + tx] =
            f2tf(s[tx][ty + 8 * i]);
}

// W2flat[k][h] -> g_w2t[h][k]  (tf32-rounded, stride K2P)
__global__ void k_tr2(const float* __restrict__ w2) {
    __shared__ float s[32][33];
    const int tx = threadIdx.x, ty = threadIdx.y;
    const int h0 = blockIdx.x * 32, k0 = blockIdx.y * 32;
    #pragma unroll
    for (int i = 0; i < 4; i++)
        s[ty + 8 * i][tx] = w2[(size_t)(k0 + ty + 8 * i) * HID + h0 + tx];
    __syncthreads();
    #pragma unroll
    for (int i = 0; i < 4; i++)
        ((uint32_t*)g_w2t)[(size_t)(h0 + ty + 8 * i) * K2P + k0 + tx] =
            f2tf(s[tx][ty + 8 * i]);
}

// fused: x -> tf32 g_xc  AND  K-tail init for g_fw / g_w2t
__global__ void k_misc(const float* __restrict__ x, const float* __restrict__ rw,
                       const float* __restrict__ b2) {
    const int b = blockIdx.x;
    if (b < 2048) {
        const size_t base = (size_t)b * 2048 + threadIdx.x * 8;
        #pragma unroll
        for (int i = 0; i < 2; i++) {
            float4 v = *(const float4*)(x + base + i * 4);
            *(uint4*)((uint32_t*)g_xc + base + i * 4) =
                make_uint4(f2tf(v.x), f2tf(v.y), f2tf(v.z), f2tf(v.w));
        }
    } else {
        const int row = b - 2048;          // 0..2047
        const int t = threadIdx.x;
        if (t < 32)
            ((uint32_t*)g_fw)[(size_t)row * K2P + K2 + t] =
                (t < 8) ? f2tf(rw[row * EXP + t]) : 0u;
        else if (t < 64) {
            const int j = t - 32;
            ((uint32_t*)g_w2t)[(size_t)row * K2P + K2 + j] =
                (j < 8) ? f2tf(b2[j * HID + row]) : 0u;
        }
    }
}

// ===================== launch =====================
extern "C" void kernel_launch(void* const* d_in, const int* in_sizes, int n_in,
                              void* d_out, int out_size) {
    const float* x  = (const float*)d_in[0];
    const float* rw = (const float*)d_in[1];
    const float* w1 = (const float*)d_in[2];
    const float* b1 = (const float*)d_in[3];
    const float* w2 = (const float*)d_in[4];
    const float* b2 = (const float*)d_in[5];
    float* out = (float*)d_out;

    cudaFuncSetAttribute(k_gemm1, cudaFuncAttributeMaxDynamicSharedMemorySize, SMEM_SZ);
    cudaFuncSetAttribute(k_gemm2, cudaFuncAttributeMaxDynamicSharedMemorySize, SMEM_SZ);

    k_tr1 <<<dim3(N1 / 32, HID / 32, EXP), dim3(32, 8)>>>(w1);
    k_tr2 <<<dim3(HID / 32, K2 / 32), dim3(32, 8)>>>(w2);
    k_misc<<<4096, 256>>>(x, rw, b2);

    k_gemm1<<<dim3(T_TOK / BM, N1 / BN, EXP), NTHR, SMEM_SZ>>>(b1, rw);
    k_gemm2<<<dim3(T_TOK / BM, HID / BN), NTHR, SMEM_SZ>>>(out);
}

// round 16
// speedup vs baseline: 2.0484x; 1.8525x over previous
#include <cuda_runtime.h>
#include <cuda_fp16.h>
#include <cstdint>

// ---- problem dims ----
#define T_TOK 2048
#define HID   2048
#define EXP   8
#define N1    4096
#define K2    16384
#define K2P   16448   // K2 + 64: bias folded into K (cols 16384..16391 = rw / down_b, rest 0)

// ---- tiling (fp16) ----
constexpr int BM = 128, BN = 128, BK = 64;   // BK in halves (128B rows)
constexpr int NTHR = 256;             // 8 warps: 4 (m) x 2 (n), warp tile 32x64
constexpr int NSTG = 3;
constexpr int RSTRB = 144;            // bytes/row: 128 data + 16 pad (conflict-free ldsm)
constexpr int ABYTES = BM * RSTRB;          // 18432
constexpr int BBYTES = BN * RSTRB;          // 18432
constexpr int STG = ABYTES + BBYTES;        // 36864
constexpr int SMEM_SZ = NSTG * STG;         // 110592  -> 2 CTAs / SM

// ---- scratch (device globals; allocation forbidden) ----
__device__ __align__(1024) __half g_xh [(size_t)T_TOK * HID];      // fp16 x
__device__ __align__(1024) __half g_w1h[(size_t)EXP * N1 * HID];   // [e][n][h]
__device__ __align__(1024) __half g_w2h[(size_t)HID * K2P];        // [h][k] (+bias tail)
__device__ __align__(1024) __half g_fwh[(size_t)T_TOK * K2P];      // rw-scaled GLU (+rw tail)

// ===================== helpers =====================
__device__ __forceinline__ uint32_t smem_u32(const void* p) {
    uint32_t a;
    asm("{ .reg .u64 t; cvta.to.shared.u64 t, %1; cvt.u32.u64 %0, t; }" : "=r"(a) : "l"(p));
    return a;
}
__device__ __forceinline__ void mma16(float* c, const uint32_t* a, const uint32_t* b) {
    asm volatile(
        "mma.sync.aligned.m16n8k16.row.col.f32.f16.f16.f32 "
        "{%0,%1,%2,%3}, {%4,%5,%6,%7}, {%8,%9}, {%0,%1,%2,%3};"
        : "+f"(c[0]), "+f"(c[1]), "+f"(c[2]), "+f"(c[3])
        : "r"(a[0]), "r"(a[1]), "r"(a[2]), "r"(a[3]), "r"(b[0]), "r"(b[1]));
}
__device__ __forceinline__ void ldsm4(uint32_t* r, uint32_t addr) {
    asm volatile("ldmatrix.sync.aligned.m8n8.x4.shared.b16 {%0,%1,%2,%3}, [%4];"
                 : "=r"(r[0]), "=r"(r[1]), "=r"(r[2]), "=r"(r[3]) : "r"(addr));
}
__device__ __forceinline__ void cp16(uint32_t s, const void* g) {
    asm volatile("cp.async.cg.shared.global [%0], [%1], 16;" :: "r"(s), "l"(g) : "memory");
}
__device__ __forceinline__ void cp_commit() {
    asm volatile("cp.async.commit_group;" ::: "memory");
}
__device__ __forceinline__ void cp_wait1() {
    asm volatile("cp.async.wait_group 1;" ::: "memory");
}

// ===================== main GEMM loop =====================
// fp16 m16n8k16, 8 warps, warp tile 32x64, B fragments double-buffered across kk.
// One __syncthreads per k-step; at iter s we write stage (s-1)%3 (reads done) -> safe.
// pA: BM rows x lda halves (k-contiguous fp16). pB: BN rows x lda halves.
__device__ __forceinline__ void gemm_main(
    const __half* __restrict__ pA, const __half* __restrict__ pB,
    size_t lda, int NK, uint32_t su, float acc[2][8][4])
{
    const int tid  = threadIdx.x;
    const int lane = tid & 31;
    const int w    = tid >> 5;
    const int wm   = (w & 3) * 32;    // 4 m-warps
    const int wn   = (w >> 2) * 64;   // 2 n-warps

    // -- cp.async addressing: 8 threads per 128B row --
    const int rr = tid >> 3;            // 0..31 (base row, +32 per rep)
    const int q  = tid & 7;             // 16B quad in row
    const __half*  asrc = pA + (size_t)rr * lda + q * 8;
    const __half*  bsrc = pB + (size_t)rr * lda + q * 8;
    const uint32_t adst = su + rr * RSTRB + q * 16;
    const uint32_t bdst = su + ABYTES + rr * RSTRB + q * 16;
    const size_t gstep = (size_t)lda * 32;       // 32 rows, in halves

    auto load_stage = [&](int s, int st) {
        const uint32_t o = st * STG;
        const size_t ko = (size_t)s * BK;
        #pragma unroll
        for (int i = 0; i < 4; i++)                       // A: 128 rows
            cp16(adst + o + i * 32 * RSTRB, asrc + ko + i * gstep);
        #pragma unroll
        for (int i = 0; i < 4; i++)                       // B: 128 rows
            cp16(bdst + o + i * 32 * RSTRB, bsrc + ko + i * gstep);
    };

    // -- ldmatrix per-lane offsets (bytes, rel. to stage base) --
    // A (16x16 frag): lanes 0-7 rows r0-7 @k0 | 8-15 rows r8-15 @k0 | 16-23 r0-7 @k8 | 24-31 r8-15 @k8
    const int la = lane & 7, lb = (lane >> 3) & 1, lc = (lane >> 4) & 1;
    const uint32_t aoff0 = (wm + la + 8 * lb) * RSTRB + lc * 16;
    const uint32_t aoff1 = aoff0 + 16 * RSTRB;
    // B (n16 x k16 per ldsm.x4): lanes 0-7 n0-7 @k0 | 8-15 n0-7 @k8 | 16-23 n8-15 @k0 | 24-31 n8-15 @k8
    uint32_t boff[4];
    #pragma unroll
    for (int p = 0; p < 4; p++)
        boff[p] = ABYTES + (wn + p * 16 + la + 8 * lc) * RSTRB + lb * 16;

    // B fragment double buffer (A loaded per-kk)
    uint32_t bf[2][4][4];
    auto ldbf = [&](int buf, uint32_t sa, int kk) {
        #pragma unroll
        for (int p = 0; p < 4; p++)
            ldsm4(bf[buf][p], sa + boff[p] + kk * 32);
    };

    // -- prologue: stages 0,1 --
    load_stage(0, 0); cp_commit();
    load_stage(1, 1); cp_commit();

    int st = 0;                      // current compute stage
    int wst = 2;                     // stage slot to write next
    #pragma unroll 1
    for (int s = 0; s < NK; ++s) {
        cp_wait1();            // oldest outstanding stage (s) resident
        __syncthreads();       // all warps done reading stage (s-1)%3

        if (s + 2 < NK)
            load_stage(s + 2, wst);
        cp_commit();

        const uint32_t sa = su + st * STG;
        ldbf(0, sa, 0);
        #pragma unroll
        for (int kk = 0; kk < 4; ++kk) {     // 4 x k16 = BK 64
            uint32_t af[2][4];
            ldsm4(af[0], sa + aoff0 + kk * 32);
            ldsm4(af[1], sa + aoff1 + kk * 32);
            if (kk < 3) ldbf((kk + 1) & 1, sa, kk + 1);
            #pragma unroll
            for (int mt = 0; mt < 2; mt++)
                #pragma unroll
                for (int nt = 0; nt < 8; nt++)
                    mma16(acc[mt][nt], af[mt], &bf[kk & 1][nt >> 1][(nt & 1) * 2]);
        }
        if (++st == NSTG) st = 0;
        if (++wst == NSTG) wst = 0;
    }
}

// ===================== GEMM1: xh @ W1h -> GLU -> g_fwh =====================
__global__ __launch_bounds__(NTHR, 2) void k_gemm1(
    const float* __restrict__ b1, const float* __restrict__ rw)
{
    extern __shared__ char smraw[];
    const uint32_t su = smem_u32(smraw);
    const int m0 = blockIdx.x * BM;
    const int n0 = blockIdx.y * BN;
    const int e  = blockIdx.z;

    float acc[2][8][4];
    #pragma unroll
    for (int a = 0; a < 2; a++)
        #pragma unroll
        for (int b = 0; b < 8; b++)
            #pragma unroll
            for (int q = 0; q < 4; q++) acc[a][b][q] = 0.f;

    gemm_main(g_xh + (size_t)m0 * HID,
              g_w1h + ((size_t)e * N1 + n0) * HID,
              HID, HID / BK, su, acc);

    const int lane = threadIdx.x & 31, w = threadIdx.x >> 5;
    const int wm = (w & 3) * 32, wn = (w >> 2) * 64;
    #pragma unroll
    for (int mt = 0; mt < 2; mt++) {
        const int r = m0 + wm + mt * 16 + (lane >> 2);
        const float rwa = rw[r * EXP + e];
        const float rwb = rw[(r + 8) * EXP + e];
        #pragma unroll
        for (int nt = 0; nt < 8; nt++) {
            const int cn = n0 + wn + nt * 8 + (lane & 3) * 2;  // even = gate
            const float bg = b1[e * N1 + cn];
            const float bu = b1[e * N1 + cn + 1];
            const int d = cn >> 1;
            {
                float g = fminf(acc[mt][nt][0] + bg, 7.f);
                float u = fminf(fmaxf(acc[mt][nt][1] + bu, -7.f), 7.f);
                float glu = g / (1.f + __expf(-1.702f * g));
                g_fwh[(size_t)r * K2P + e * 2048 + d] = __float2half_rn((u + 1.f) * glu * rwa);
            }
            {
                float g = fminf(acc[mt][nt][2] + bg, 7.f);
                float u = fminf(fmaxf(acc[mt][nt][3] + bu, -7.f), 7.f);
                float glu = g / (1.f + __expf(-1.702f * g));
                g_fwh[(size_t)(r + 8) * K2P + e * 2048 + d] = __float2half_rn((u + 1.f) * glu * rwb);
            }
        }
    }
}

// ===================== GEMM2: g_fwh @ W2h (bias in K-tail) -> out =====================
__global__ __launch_bounds__(NTHR, 2) void k_gemm2(float* __restrict__ out)
{
    extern __shared__ char smraw[];
    const uint32_t su = smem_u32(smraw);
    const int m0 = blockIdx.x * BM;
    const int n0 = blockIdx.y * BN;

    float acc[2][8][4];
    #pragma unroll
    for (int a = 0; a < 2; a++)
        #pragma unroll
        for (int b = 0; b < 8; b++)
            #pragma unroll
            for (int q = 0; q < 4; q++) acc[a][b][q] = 0.f;

    gemm_main(g_fwh + (size_t)m0 * K2P,
              g_w2h + (size_t)n0 * K2P,
              K2P, K2P / BK, su, acc);     // 257 k-steps

    const int lane = threadIdx.x & 31, w = threadIdx.x >> 5;
    const int wm = (w & 3) * 32, wn = (w >> 2) * 64;
    #pragma unroll
    for (int mt = 0; mt < 2; mt++) {
        const int r = m0 + wm + mt * 16 + (lane >> 2);
        #pragma unroll
        for (int nt = 0; nt < 8; nt++) {
            const int cn = n0 + wn + nt * 8 + (lane & 3) * 2;
            *(float2*)&out[(size_t)r * HID + cn] =
                make_float2(acc[mt][nt][0], acc[mt][nt][1]);
            *(float2*)&out[(size_t)(r + 8) * HID + cn] =
                make_float2(acc[mt][nt][2], acc[mt][nt][3]);
        }
    }
}

// ===================== prepass =====================
// W1[e][h][n] -> g_w1h[e][n][h]  (fp16)
__global__ void k_tr1(const float* __restrict__ w1) {
    __shared__ float s[32][33];
    const int tx = threadIdx.x, ty = threadIdx.y;
    const int n0 = blockIdx.x * 32, h0 = blockIdx.y * 32, e = blockIdx.z;
    #pragma unroll
    for (int i = 0; i < 4; i++)
        s[ty + 8 * i][tx] = w1[((size_t)e * HID + h0 + ty + 8 * i) * N1 + n0 + tx];
    __syncthreads();
    #pragma unroll
    for (int i = 0; i < 4; i++)
        g_w1h[((size_t)e * N1 + n0 + ty + 8 * i) * HID + h0 + tx] =
            __float2half_rn(s[tx][ty + 8 * i]);
}

// W2flat[k][h] -> g_w2h[h][k]  (fp16, row stride K2P)
__global__ void k_tr2(const float* __restrict__ w2) {
    __shared__ float s[32][33];
    const int tx = threadIdx.x, ty = threadIdx.y;
    const int h0 = blockIdx.x * 32, k0 = blockIdx.y * 32;
    #pragma unroll
    for (int i = 0; i < 4; i++)
        s[ty + 8 * i][tx] = w2[(size_t)(k0 + ty + 8 * i) * HID + h0 + tx];
    __syncthreads();
    #pragma unroll
    for (int i = 0; i < 4; i++)
        g_w2h[(size_t)(h0 + ty + 8 * i) * K2P + k0 + tx] =
            __float2half_rn(s[tx][ty + 8 * i]);
}

// fused: x -> fp16 g_xh  AND  K-tail init (64 cols) for g_fwh / g_w2h
__global__ void k_misc(const float* __restrict__ x, const float* __restrict__ rw,
                       const float* __restrict__ b2) {
    const int b = blockIdx.x;
    if (b < 2048) {
        const size_t base = (size_t)b * 2048 + threadIdx.x * 8;
        #pragma unroll
        for (int i = 0; i < 2; i++) {
            float4 v = *(const float4*)(x + base + i * 4);
            __half2* dst = (__half2*)(g_xh + base + i * 4);
            dst[0] = __floats2half2_rn(v.x, v.y);
            dst[1] = __floats2half2_rn(v.z, v.w);
        }
    } else {
        const int row = b - 2048;          // 0..2047
        const int t = threadIdx.x;
        if (t < 64)
            g_fwh[(size_t)row * K2P + K2 + t] =
                (t < 8) ? __float2half_rn(rw[row * EXP + t]) : __float2half_rn(0.f);
        else if (t < 128) {
            const int j = t - 64;
            g_w2h[(size_t)row * K2P + K2 + j] =
                (j < 8) ? __float2half_rn(b2[j * HID + row]) : __float2half_rn(0.f);
        }
    }
}

// ===================== launch =====================
extern "C" void kernel_launch(void* const* d_in, const int* in_sizes, int n_in,
                              void* d_out, int out_size) {
    const float* x  = (const float*)d_in[0];
    const float* rw = (const float*)d_in[1];
    const float* w1 = (const float*)d_in[2];
    const float* b1 = (const float*)d_in[3];
    const float* w2 = (const float*)d_in[4];
    const float* b2 = (const float*)d_in[5];
    float* out = (float*)d_out;

    cudaFuncSetAttribute(k_gemm1, cudaFuncAttributeMaxDynamicSharedMemorySize, SMEM_SZ);
    cudaFuncSetAttribute(k_gemm2, cudaFuncAttributeMaxDynamicSharedMemorySize, SMEM_SZ);

    k_tr1 <<<dim3(N1 / 32, HID / 32, EXP), dim3(32, 8)>>>(w1);
    k_tr2 <<<dim3(HID / 32, K2 / 32), dim3(32, 8)>>>(w2);
    k_misc<<<4096, 256>>>(x, rw, b2);

    k_gemm1<<<dim3(T_TOK / BM, N1 / BN, EXP), NTHR, SMEM_SZ>>>(b1, rw);
    k_gemm2<<<dim3(T_TOK / BM, HID / BN), NTHR, SMEM_SZ>>>(out);
}